// round 12
// baseline (speedup 1.0000x reference)
#include <cuda_runtime.h>

// Problem constants (fixed by reference)
#define CN 64
#define HN 256
#define WN 256
#define L0N 1024   // g0 length (y samples), output innermost dim (j)
#define L1N 1024   // g1 length (x samples), output middle dim (i)
#define AC (-0.75f)

#define JT 128       // j-tile width per block
#define NB 256       // x0 bins
#define NSPLIT 2     // bin-range splits per (c, j-tile)
#define SROW 132     // floats per smem row: S4=33 (odd) -> conflict-free STS
                     // (lanes along x, stride 33 quads) AND LDS.128 (contiguous)
#define NROWS 131    // rows x_abs in [spbase-1, spbase+129], borders duplicated

// Precomputed y tap indices / weights
__device__ int4   g_yidx[L0N];
__device__ float4 g_ywt [L0N];
// x samples sorted by x0 bin
__device__ int    g_binstart[NB + 1];
__device__ int    g_meta[L1N];   // i | (bin << 16), sorted by bin
__device__ float4 g_swx [L1N];   // weights, sorted by bin

__device__ __forceinline__ void cubic_w(float t, float* w) {
    // Matches reference _cubic_weights exactly (A = -0.75)
    float t2 = t * t;
    float t3 = t2 * t;
    w[0] = AC * (t3 - 2.0f * t2 + t);
    w[1] = (AC + 2.0f) * t3 - (AC + 3.0f) * t2 + 1.0f;
    float s  = 1.0f - t;
    float s2 = s * s;
    w[2] = (AC + 2.0f) * s2 * s - (AC + 3.0f) * s2 + 1.0f;
    float u = 1.0f + s;
    w[3] = AC * (u * u * u) - 5.0f * AC * (u * u) + 8.0f * AC * u - 4.0f * AC;
}

// Single-block prep: y tables + counting sort of x samples by x0 (parallel scan).
__global__ void prep_kernel(const float* __restrict__ g0,
                            const float* __restrict__ g1) {
    __shared__ int sh_hist[NB];
    __shared__ int sh_scan[NB];
    __shared__ int sh_base[NB];
    const int tid = threadIdx.x;   // 0..1023

    // --- y taps ---
    {
        float x  = (g0[tid] + 1.0f) * 0.5f * (float)(HN - 1);
        float x0 = floorf(x);
        float t  = x - x0;
        int  i0  = (int)x0;
        float w[4];
        cubic_w(t, w);
        int idx[4];
#pragma unroll
        for (int b = 0; b < 4; b++) idx[b] = min(max(i0 - 1 + b, 0), HN - 1);
        g_yidx[tid] = make_int4(idx[0], idx[1], idx[2], idx[3]);
        g_ywt [tid] = make_float4(w[0], w[1], w[2], w[3]);
    }

    // --- x taps: bin by x0, counting sort ---
    float x  = (g1[tid] + 1.0f) * 0.5f * (float)(WN - 1);
    float x0 = floorf(x);
    float t  = x - x0;
    int bin  = min(max((int)x0, 0), NB - 1);
    float w[4];
    cubic_w(t, w);

    if (tid < NB) sh_hist[tid] = 0;
    __syncthreads();
    int rank = atomicAdd(&sh_hist[bin], 1);
    __syncthreads();

    // Parallel inclusive scan (Hillis-Steele) over 256 bins
    if (tid < NB) sh_scan[tid] = sh_hist[tid];
    __syncthreads();
#pragma unroll
    for (int off = 1; off < NB; off <<= 1) {
        int v = 0;
        if (tid < NB && tid >= off) v = sh_scan[tid - off];
        __syncthreads();
        if (tid < NB) sh_scan[tid] += v;
        __syncthreads();
    }
    if (tid < NB) {
        int base = sh_scan[tid] - sh_hist[tid];   // exclusive
        sh_base[tid] = base;
        g_binstart[tid] = base;
        if (tid == NB - 1) g_binstart[NB] = sh_scan[tid];
    }
    __syncthreads();

    int pos = sh_base[bin] + rank;
    g_swx [pos] = make_float4(w[0], w[1], w[2], w[3]);
    g_meta[pos] = tid | (bin << 16);
}

// Fused kernel: one block = (c, 128-wide j tile, half of x0-bins). 512 thr.
// smem: sY[sr][j], sr = x_abs - (spbase-1), border rows physically duplicated
// (phase A clamps the SOURCE index) -> phase B needs no clamping at all.
// Phase B: warps take equal slices of the sorted entry list (perfect balance)
// and keep the 4 tap rows in float4 registers, advancing by warp-uniform
// rotation when the bin changes (~0.5 LDS.128 per entry amortized).
__global__ void __launch_bounds__(512, 3)
fused_kernel(const float* __restrict__ v, float* __restrict__ out) {
    extern __shared__ float sY[];          // [NROWS][SROW]

    const int tid  = threadIdx.x;
    const int lane = tid & 31;
    const int wid  = tid >> 5;             // 0..15
    const int jt = blockIdx.x * JT;        // j tile base
    const int c  = blockIdx.y;
    const int sp = blockIdx.z;             // bin split 0/1
    const int spbase = sp << 7;            // first bin of this split

    const float* vc = v + (size_t)c * (HN * WN);

    // ---- Phase A: y-interpolation into smem (low-register form) ----
    // smem row sr holds x_abs = spbase - 1 + sr, source-clamped to [0,255].
#pragma unroll
    for (int jj = 0; jj < 8; jj++) {
        const int jl = (wid << 3) + jj;    // 0..127
        const int4   yi = g_yidx[jt + jl];
        const float4 wy = g_ywt [jt + jl];
        const float* r0 = vc + yi.x * WN;
        const float* r1 = vc + yi.y * WN;
        const float* r2 = vc + yi.z * WN;
        const float* r3 = vc + yi.w * WN;
#pragma unroll
        for (int xc = 0; xc < 5; xc++) {
            const int sr = xc * 32 + lane;
            if (sr < NROWS) {
                const int xs = min(max(spbase - 1 + sr, 0), WN - 1);
                float acc = wy.x * __ldg(r0 + xs)
                          + wy.y * __ldg(r1 + xs)
                          + wy.z * __ldg(r2 + xs)
                          + wy.w * __ldg(r3 + xs);
                sY[sr * SROW + jl] = acc;
            }
        }
    }
    __syncthreads();

    // ---- Phase B: balanced sorted-entry sweep with uniform rotation ----
    float* outc = out + ((size_t)c * L1N) * L0N + jt + (lane << 2);
    const float* srow = sY + (lane << 2);
    // bin b (local bl = b - spbase) needs smem rows bl, bl+1, bl+2, bl+3.
    #define LOADROW(sr) (*(const float4*)(srow + (sr) * SROW))

    const int s0  = g_binstart[spbase];
    const int cnt = g_binstart[spbase + 128] - s0;
    int       k   = s0 + ((cnt * wid) >> 4);
    const int ke  = s0 + ((cnt * (wid + 1)) >> 4);

    int cur = -1000;
    float4 a0, a1, a2, a3;

#pragma unroll 1
    for (; k < ke; k++) {
        const int    meta = g_meta[k];
        const float4 wx   = g_swx [k];
        const int i  = meta & 0xFFFF;
        const int bl = (meta >> 16) - spbase;
        const int d  = bl - cur;
        if (d != 0) {
            if (d == 1) {
                a0 = a1; a1 = a2; a2 = a3; a3 = LOADROW(bl + 3);
            } else if (d == 2) {
                a0 = a2; a1 = a3; a2 = LOADROW(bl + 2); a3 = LOADROW(bl + 3);
            } else {
                a0 = LOADROW(bl);     a1 = LOADROW(bl + 1);
                a2 = LOADROW(bl + 2); a3 = LOADROW(bl + 3);
            }
            cur = bl;
        }
        float4 acc;
        acc.x = wx.x * a0.x + wx.y * a1.x + wx.z * a2.x + wx.w * a3.x;
        acc.y = wx.x * a0.y + wx.y * a1.y + wx.z * a2.y + wx.w * a3.y;
        acc.z = wx.x * a0.z + wx.y * a1.z + wx.z * a2.z + wx.w * a3.z;
        acc.w = wx.x * a0.w + wx.y * a1.w + wx.z * a2.w + wx.w * a3.w;
        *(float4*)(outc + (size_t)i * L0N) = acc;
    }
    #undef LOADROW
}

extern "C" void kernel_launch(void* const* d_in, const int* in_sizes, int n_in,
                              void* d_out, int out_size) {
    const float* values = (const float*)d_in[0];   // (1,64,256,256)
    const float* g0     = (const float*)d_in[1];   // (1024,)
    const float* g1     = (const float*)d_in[2];   // (1024,)
    float* out = (float*)d_out;                    // (1,64,1024,1024)

    static int smem_set = 0;
    const int smem_bytes = NROWS * SROW * sizeof(float);  // 131*132*4 = 69168
    if (!smem_set) {
        cudaFuncSetAttribute(fused_kernel,
                             cudaFuncAttributeMaxDynamicSharedMemorySize,
                             smem_bytes);
        smem_set = 1;
    }

    prep_kernel<<<1, 1024>>>(g0, g1);

    dim3 grid(L0N / JT, CN, NSPLIT);       // (8, 64, 2) = 1024 blocks
    fused_kernel<<<grid, 512, smem_bytes>>>(values, out);
}

// round 13
// speedup vs baseline: 1.1736x; 1.1736x over previous
#include <cuda_runtime.h>

// Problem constants (fixed by reference)
#define CN 64
#define HN 256
#define WN 256
#define L0N 1024   // g0 length (y samples), output innermost dim (j)
#define L1N 1024   // g1 length (x samples), output middle dim (i)
#define AC (-0.75f)

#define JT 128     // j-tile width per block (one float4 per lane)
#define NB 256     // x0 bins
#define SROW 132   // floats per smem row: 33 quads (odd) -> conflict-free
                   // STS.128 (lanes along x) AND LDS.128 (lanes along f)
#define NWARP 32   // warps per block

// Precomputed y tap indices / weights
__device__ int4   g_yidx[L0N];
__device__ float4 g_ywt [L0N];
// x samples sorted by x0 bin (counting sort)
__device__ int    g_binstart[NB + 1];
__device__ float4 g_swx[L1N];        // weights in sorted order
__device__ int    g_si [L1N];        // original i in sorted order
__device__ int    g_wstart[NWARP + 1]; // balanced bin partition (by entries)

// smem float offsets
#define OFF_SY   0
#define OFF_SWX  (HN * SROW)             // 33792, 16B aligned
#define OFF_SI   (OFF_SWX + L1N * 4)     // 37888
#define OFF_BS   (OFF_SI + L1N)          // 38912
#define OFF_WS   (OFF_BS + NB + 1)       // 39169
#define SMEM_FLOATS (OFF_WS + NWARP + 1) // 39202

__device__ __forceinline__ void cubic_w(float t, float* w) {
    // Matches reference _cubic_weights exactly (A = -0.75)
    float t2 = t * t;
    float t3 = t2 * t;
    w[0] = AC * (t3 - 2.0f * t2 + t);
    w[1] = (AC + 2.0f) * t3 - (AC + 3.0f) * t2 + 1.0f;
    float s  = 1.0f - t;
    float s2 = s * s;
    w[2] = (AC + 2.0f) * s2 * s - (AC + 3.0f) * s2 + 1.0f;
    float u = 1.0f + s;
    w[3] = AC * (u * u * u) - 5.0f * AC * (u * u) + 8.0f * AC * u - 4.0f * AC;
}

// Single-block prep: y tables + counting sort + balanced warp partition.
__global__ void prep_kernel(const float* __restrict__ g0,
                            const float* __restrict__ g1) {
    __shared__ int sh_hist[NB];
    __shared__ int sh_scan[NB];
    __shared__ int sh_base[NB];
    const int tid = threadIdx.x;   // 0..1023

    // --- y taps ---
    {
        float x  = (g0[tid] + 1.0f) * 0.5f * (float)(HN - 1);
        float x0 = floorf(x);
        float t  = x - x0;
        int  i0  = (int)x0;
        float w[4];
        cubic_w(t, w);
        int idx[4];
#pragma unroll
        for (int b = 0; b < 4; b++) idx[b] = min(max(i0 - 1 + b, 0), HN - 1);
        g_yidx[tid] = make_int4(idx[0], idx[1], idx[2], idx[3]);
        g_ywt [tid] = make_float4(w[0], w[1], w[2], w[3]);
    }

    // --- x taps: bin by x0, counting sort ---
    float x  = (g1[tid] + 1.0f) * 0.5f * (float)(WN - 1);
    float x0 = floorf(x);
    float t  = x - x0;
    int bin  = min(max((int)x0, 0), NB - 1);
    float w[4];
    cubic_w(t, w);

    if (tid < NB) sh_hist[tid] = 0;
    __syncthreads();
    int rank = atomicAdd(&sh_hist[bin], 1);
    __syncthreads();

    // Parallel inclusive scan (Hillis-Steele) over 256 bins
    if (tid < NB) sh_scan[tid] = sh_hist[tid];
    __syncthreads();
#pragma unroll
    for (int off = 1; off < NB; off <<= 1) {
        int v = 0;
        if (tid < NB && tid >= off) v = sh_scan[tid - off];
        __syncthreads();
        if (tid < NB) sh_scan[tid] += v;
        __syncthreads();
    }
    if (tid < NB) {
        int base = sh_scan[tid] - sh_hist[tid];   // exclusive
        sh_base[tid] = base;
        g_binstart[tid] = base;
        if (tid == NB - 1) g_binstart[NB] = sh_scan[tid];
    }
    __syncthreads();

    int pos = sh_base[bin] + rank;
    g_swx[pos] = make_float4(w[0], w[1], w[2], w[3]);
    g_si [pos] = tid;

    // --- balanced warp partition: wstart[q] = bin containing entry q*32 ---
    if (tid <= NWARP) {
        const int target = tid * (L1N / NWARP);
        int lo = 0, hi = NB;
        while (lo < hi) {
            int mid = (lo + hi) >> 1;
            // sh_base[mid] + hist = inclusive end of bin mid
            int endv = (mid == NB - 1) ? L1N : sh_base[mid + 1];
            if (endv > target) hi = mid; else lo = mid + 1;
        }
        g_wstart[tid] = lo;   // tid==NWARP -> 256
    }
}

// Fused kernel: one block = (c, 128-wide j tile), 1024 threads.
// Phase A: warp w owns f-group f=w. Per x: 16 independent coalesced LDG.32
//          (MLP=16) -> one conflict-free STS.128 (odd quad stride, no swizzle).
//          Meanwhile tables (si, swx, binstart, wstart) are copied to smem.
// Phase B: warp w sweeps bins [wstart[w], wstart[w+1]) — a BALANCED contiguous
//          range (~32 entries) — with pure float4 register rotation
//          (1 conflict-free LDS.128 per bin, zero branches, unroll-2 k-loop).
__global__ void __launch_bounds__(1024, 1)
fused_kernel(const float* __restrict__ v, float* __restrict__ out) {
    extern __shared__ float smem[];
    float* sY   = smem + OFF_SY;           // [256][132]
    float4* sWX = (float4*)(smem + OFF_SWX);
    int*   sSI  = (int*)(smem + OFF_SI);
    int*   sBS  = (int*)(smem + OFF_BS);
    int*   sWS  = (int*)(smem + OFF_WS);

    const int tid  = threadIdx.x;
    const int lane = tid & 31;
    const int wid  = tid >> 5;             // 0..31
    const int jt = blockIdx.x * JT;        // j tile base
    const int c  = blockIdx.y;

    const float* vc = v + (size_t)c * (HN * WN);

    // ---- table copy (no divergence cost; overlaps phase-A loads) ----
    sWX[tid] = g_swx[tid];
    sSI[tid] = g_si[tid];
    if (tid < NB + 1) sBS[tid] = g_binstart[tid];
    if (tid < NWARP + 1) sWS[tid] = g_wstart[tid];

    // ---- Phase A: y-interpolation into smem ----
    {
        const int f  = wid;                // f-group 0..31
        const int jl = f << 2;
        const int4   yi0 = g_yidx[jt + jl + 0];
        const int4   yi1 = g_yidx[jt + jl + 1];
        const int4   yi2 = g_yidx[jt + jl + 2];
        const int4   yi3 = g_yidx[jt + jl + 3];
        const float4 wy0 = g_ywt [jt + jl + 0];
        const float4 wy1 = g_ywt [jt + jl + 1];
        const float4 wy2 = g_ywt [jt + jl + 2];
        const float4 wy3 = g_ywt [jt + jl + 3];
#pragma unroll
        for (int xc = 0; xc < 8; xc++) {
            const int x = xc * 32 + lane;
            const float* px = vc + x;
            float4 st;
            st.x = wy0.x * __ldg(px + yi0.x * WN) + wy0.y * __ldg(px + yi0.y * WN)
                 + wy0.z * __ldg(px + yi0.z * WN) + wy0.w * __ldg(px + yi0.w * WN);
            st.y = wy1.x * __ldg(px + yi1.x * WN) + wy1.y * __ldg(px + yi1.y * WN)
                 + wy1.z * __ldg(px + yi1.z * WN) + wy1.w * __ldg(px + yi1.w * WN);
            st.z = wy2.x * __ldg(px + yi2.x * WN) + wy2.y * __ldg(px + yi2.y * WN)
                 + wy2.z * __ldg(px + yi2.z * WN) + wy2.w * __ldg(px + yi2.w * WN);
            st.w = wy3.x * __ldg(px + yi3.x * WN) + wy3.y * __ldg(px + yi3.y * WN)
                 + wy3.z * __ldg(px + yi3.z * WN) + wy3.w * __ldg(px + yi3.w * WN);
            *(float4*)(sY + x * SROW + (f << 2)) = st;
        }
    }
    __syncthreads();

    // ---- Phase B: balanced bin ranges, pure register rotation ----
    float* outc = out + ((size_t)c * L1N) * L0N + jt + (lane << 2);
    const float* srow = sY + (lane << 2);
    #define LOADROW(xx) (*(const float4*)(srow + (xx) * SROW))

    const int bs = sWS[wid];
    const int be = sWS[wid + 1];
    if (bs < be) {
        float4 a0 = LOADROW(max(bs - 1, 0));
        float4 a1 = LOADROW(bs);
        float4 a2 = LOADROW(min(bs + 1, WN - 1));

        int s = sBS[bs];
        for (int b = bs; b < be; b++) {
            const float4 a3 = LOADROW(min(b + 2, WN - 1));
            const int e = sBS[b + 1];

            int k = s;
            for (; k + 1 < e; k += 2) {
                const int    iA  = sSI[k];
                const float4 wxA = sWX[k];
                const int    iB  = sSI[k + 1];
                const float4 wxB = sWX[k + 1];
                float4 accA, accB;
                accA.x = wxA.x * a0.x + wxA.y * a1.x + wxA.z * a2.x + wxA.w * a3.x;
                accA.y = wxA.x * a0.y + wxA.y * a1.y + wxA.z * a2.y + wxA.w * a3.y;
                accA.z = wxA.x * a0.z + wxA.y * a1.z + wxA.z * a2.z + wxA.w * a3.z;
                accA.w = wxA.x * a0.w + wxA.y * a1.w + wxA.z * a2.w + wxA.w * a3.w;
                accB.x = wxB.x * a0.x + wxB.y * a1.x + wxB.z * a2.x + wxB.w * a3.x;
                accB.y = wxB.x * a0.y + wxB.y * a1.y + wxB.z * a2.y + wxB.w * a3.y;
                accB.z = wxB.x * a0.z + wxB.y * a1.z + wxB.z * a2.z + wxB.w * a3.z;
                accB.w = wxB.x * a0.w + wxB.y * a1.w + wxB.z * a2.w + wxB.w * a3.w;
                *(float4*)(outc + (size_t)iA * L0N) = accA;
                *(float4*)(outc + (size_t)iB * L0N) = accB;
            }
            if (k < e) {
                const int    i  = sSI[k];
                const float4 wx = sWX[k];
                float4 acc;
                acc.x = wx.x * a0.x + wx.y * a1.x + wx.z * a2.x + wx.w * a3.x;
                acc.y = wx.x * a0.y + wx.y * a1.y + wx.z * a2.y + wx.w * a3.y;
                acc.z = wx.x * a0.z + wx.y * a1.z + wx.z * a2.z + wx.w * a3.z;
                acc.w = wx.x * a0.w + wx.y * a1.w + wx.z * a2.w + wx.w * a3.w;
                *(float4*)(outc + (size_t)i * L0N) = acc;
            }
            s = e;
            a0 = a1; a1 = a2; a2 = a3;
        }
    }
    #undef LOADROW
}

extern "C" void kernel_launch(void* const* d_in, const int* in_sizes, int n_in,
                              void* d_out, int out_size) {
    const float* values = (const float*)d_in[0];   // (1,64,256,256)
    const float* g0     = (const float*)d_in[1];   // (1024,)
    const float* g1     = (const float*)d_in[2];   // (1024,)
    float* out = (float*)d_out;                    // (1,64,1024,1024)

    static int smem_set = 0;
    const int smem_bytes = SMEM_FLOATS * sizeof(float);  // ~156.8 KB
    if (!smem_set) {
        cudaFuncSetAttribute(fused_kernel,
                             cudaFuncAttributeMaxDynamicSharedMemorySize,
                             smem_bytes);
        smem_set = 1;
    }

    prep_kernel<<<1, 1024>>>(g0, g1);

    dim3 grid(L0N / JT, CN);               // (8, 64) = 512 blocks
    fused_kernel<<<grid, 1024, smem_bytes>>>(values, out);
}